// round 12
// baseline (speedup 1.0000x reference)
#include <cuda_runtime.h>
#include <cstdint>

#define W      30
#define TT     4096
#define FF     128
#define NS     (TT - W + 1)        // 4067 window starts
#define SEG    60                  // outputs per CTA (2 halves of 30)
#define ROWS   (SEG + W)           // 90 staged input rows
#define UNITS  (ROWS * 32)         // 2880 16-byte units to stage
#define IN_FLOATS  (ROWS * FF)     // 11520
#define OUT_FLOATS (SEG * FF)      // 7680
#define OUT_BYTES  (OUT_FLOATS * 4) // 30720 contiguous output bytes per CTA
#define SMEM_BYTES ((IN_FLOATS + OUT_FLOATS) * 4)  // 76800 -> 2 CTAs/SM
#define EPSF   1e-4f

__device__ __forceinline__ void cp16(uint32_t saddr, const void* gaddr) {
    asm volatile("cp.async.cg.shared.global [%0], [%1], 16;" :: "r"(saddr), "l"(gaddr));
}
__device__ __forceinline__ void cp_commit() {
    asm volatile("cp.async.commit_group;");
}
template <int N>
__device__ __forceinline__ void cp_wait() {
    asm volatile("cp.async.wait_group %0;" :: "n"(N));
}

__global__ __launch_bounds__(256)
void ts_zscore_kernel(const float* __restrict__ x, float* __restrict__ out)
{
    extern __shared__ float sm[];               // [0, IN_FLOATS): input stage
    float* outsm = sm + IN_FLOATS;              // [IN_FLOATS, +OUT_FLOATS): output stage

    const int f   = threadIdx.x;        // feature 0..127
    const int h   = threadIdx.y;        // half 0..1 (outputs [h*30, h*30+30))
    const int tid = threadIdx.y * FF + threadIdx.x;
    const int b   = blockIdx.x;

    int k0 = blockIdx.y * SEG;
    if (k0 > NS - SEG) k0 = NS - SEG;   // tail block overlaps prior (same values)

    const uint32_t sbase = (uint32_t)__cvta_generic_to_shared(sm);
    const float* __restrict__ xb = x + (size_t)b * TT * FF;

    // Stage 90 input rows (k0 .. k0+89): 2880 16B units over 256 threads.
    // Row k0+89 may exceed the tensor by one (k0 max = 4007) — clamp; never consumed.
#pragma unroll
    for (int i = 0; i < 12; ++i) {
        const int idx = tid + i * 256;
        if (i < 11 || idx < UNITS) {
            int grow = k0 + (idx >> 5);
            if (grow > TT - 1) grow = TT - 1;
            const float* g = xb + (size_t)grow * FF + ((idx & 31) << 2);
            cp16(sbase + (uint32_t)idx * 16u, g);
        }
    }
    cp_commit();

    const float* __restrict__ sg = sm + (size_t)(h * W) * FF + f;   // this half's rows
    float* __restrict__ osg = outsm + (size_t)(h * W) * FF + f;     // this half's outputs

    cp_wait<0>();
    __syncthreads();

    // Prime s,s2 with local rows 0..28 of this half.
    float s = 0.0f, s2 = 0.0f;
#pragma unroll
    for (int i = 0; i < W - 1; ++i) {
        const float v = sg[i * FF];
        s += v;
        s2 = fmaf(v, v, s2);
    }

#pragma unroll
    for (int u = 0; u < W; ++u) {
        const float nv = sg[(u + W - 1) * FF];   // row entering the window

        const float ss  = s + nv;
        const float ss2 = fmaf(nv, nv, s2);

        const float mean   = ss  * (1.0f / W);
        const float meansq = ss2 * (1.0f / W);
        float var = fmaxf(fmaf(-mean, mean, meansq), 1e-12f);

        // 1/(std+eps) ~= rs*(1-eps*rs), rs = rsqrt(var); rel err ~ eps^2/var.
        float rs;
        asm("rsqrt.approx.f32 %0, %1;" : "=f"(rs) : "f"(var));
        const float r = (nv - mean) * rs * fmaf(-EPSF, rs, 1.0f);

        osg[u * FF] = r;                         // stage output in smem

        const float ov = sg[u * FF];             // row leaving the window
        s  = ss  - ov;
        s2 = fmaf(-ov, ov, ss2);
    }

    __syncthreads();   // all 60 output rows staged

    // One contiguous 30720-byte bulk store: out[b, k0 .. k0+59, :].
    if (tid == 0) {
        asm volatile("fence.proxy.async.shared::cta;" ::: "memory");
        float* gdst = out + ((size_t)b * NS + k0) * FF;
        const uint32_t ssrc = sbase + (uint32_t)(IN_FLOATS * 4);
        asm volatile(
            "cp.async.bulk.global.shared::cta.bulk_group [%0], [%1], %2;"
            :: "l"(gdst), "r"(ssrc), "r"((uint32_t)OUT_BYTES) : "memory");
        asm volatile("cp.async.bulk.commit_group;");
        // Only the smem READ must finish before this CTA's smem is reused.
        asm volatile("cp.async.bulk.wait_group.read 0;" ::: "memory");
    }
}

extern "C" void kernel_launch(void* const* d_in, const int* in_sizes, int n_in,
                              void* d_out, int out_size)
{
    (void)n_in; (void)out_size;
    const float* x = (const float*)d_in[0];
    float* out = (float*)d_out;

    cudaFuncSetAttribute(ts_zscore_kernel,
                         cudaFuncAttributeMaxDynamicSharedMemorySize, SMEM_BYTES);

    const int B = in_sizes[0] / (TT * FF);   // 64 for this problem
    dim3 block(FF, 2);                        // 256 threads
    dim3 grid(B, (NS + SEG - 1) / SEG);       // (64, 68)
    ts_zscore_kernel<<<grid, block, SMEM_BYTES>>>(x, out);
}

// round 13
// speedup vs baseline: 1.0846x; 1.0846x over previous
#include <cuda_runtime.h>
#include <cstdint>

#define W      30
#define TT     4096
#define FF     128
#define F2     (FF / 2)            // 64 float2 lanes per row
#define NS     (TT - W + 1)        // 4067 window starts
#define SEG    60                  // outputs per CTA (2 halves of 30)
#define ROWS   (SEG + W)           // 90 staged rows
#define UNITS  (ROWS * 32)         // 2880 16-byte units to stage
#define SMEM_BYTES (ROWS * FF * 4) // 46080 -> 4 CTAs/SM
#define EPSF   1e-4f

__device__ __forceinline__ void cp16(uint32_t saddr, const void* gaddr) {
    asm volatile("cp.async.cg.shared.global [%0], [%1], 16;" :: "r"(saddr), "l"(gaddr));
}
__device__ __forceinline__ void cp_commit() {
    asm volatile("cp.async.commit_group;");
}
template <int N>
__device__ __forceinline__ void cp_wait() {
    asm volatile("cp.async.wait_group %0;" :: "n"(N));
}

// ---- packed f32x2 helpers (FFMA2 path: PTX-only, ptxas won't auto-fuse) ----
__device__ __forceinline__ uint64_t f2pk(float x, float y) {
    uint64_t r; asm("mov.b64 %0, {%1, %2};" : "=l"(r) : "f"(x), "f"(y)); return r;
}
__device__ __forceinline__ float2 f2up(uint64_t p) {
    float2 v; asm("mov.b64 {%0, %1}, %2;" : "=f"(v.x), "=f"(v.y) : "l"(p)); return v;
}
__device__ __forceinline__ uint64_t f2add(uint64_t a, uint64_t b) {
    uint64_t d; asm("add.rn.f32x2 %0, %1, %2;" : "=l"(d) : "l"(a), "l"(b)); return d;
}
__device__ __forceinline__ uint64_t f2mul(uint64_t a, uint64_t b) {
    uint64_t d; asm("mul.rn.f32x2 %0, %1, %2;" : "=l"(d) : "l"(a), "l"(b)); return d;
}
__device__ __forceinline__ uint64_t f2fma(uint64_t a, uint64_t b, uint64_t c) {
    uint64_t d; asm("fma.rn.f32x2 %0, %1, %2, %3;" : "=l"(d) : "l"(a), "l"(b), "l"(c)); return d;
}

__global__ __launch_bounds__(128)
void ts_zscore_kernel(const float* __restrict__ x, float* __restrict__ out)
{
    extern __shared__ float sm[];
    const int fp  = threadIdx.x;        // feature pair 0..63
    const int h   = threadIdx.y;        // half 0..1 (outputs [h*30, h*30+30))
    const int tid = threadIdx.y * F2 + threadIdx.x;
    const int b   = blockIdx.x;

    int k0 = blockIdx.y * SEG;
    if (k0 > NS - SEG) k0 = NS - SEG;   // tail block overlaps prior (same values)

    const uint32_t sbase = (uint32_t)__cvta_generic_to_shared(sm);
    const float* __restrict__ xb = x + (size_t)b * TT * FF;

    // Stage 90 rows (k0 .. k0+89): 2880 16B units over 128 threads.
    // Row k0+89 may exceed the tensor by one (k0 max = 4007) — clamp; never consumed.
#pragma unroll
    for (int i = 0; i < 23; ++i) {
        const int idx = tid + i * 128;
        if (i < 22 || idx < UNITS) {
            int grow = k0 + (idx >> 5);
            if (grow > TT - 1) grow = TT - 1;
            const float* g = xb + (size_t)grow * FF + ((idx & 31) << 2);
            cp16(sbase + (uint32_t)idx * 16u, g);
        }
    }
    cp_commit();

    // Per-half bases in float2 units.
    const float2* __restrict__ sg = (const float2*)sm + (size_t)(h * W) * F2 + fp;
    float2* __restrict__ op =
        (float2*)out + ((size_t)b * NS + k0 + h * W) * F2 + fp;

    cp_wait<0>();
    __syncthreads();

    const uint64_t invWp  = f2pk( 1.0f / W,  1.0f / W);
    const uint64_t ninvWp = f2pk(-1.0f / W, -1.0f / W);
    const uint64_t neg1p  = f2pk(-1.0f, -1.0f);

    // Prime s,s2 (packed) with local rows 0..28 of this half.
    uint64_t sp = f2pk(0.f, 0.f), s2p = sp;
#pragma unroll
    for (int i = 0; i < W - 1; ++i) {
        const float2 v = sg[i * F2];
        const uint64_t vp = f2pk(v.x, v.y);
        sp  = f2add(sp, vp);
        s2p = f2fma(vp, vp, s2p);
    }

#pragma unroll
    for (int u = 0; u < W; ++u) {
        const float2 nv = sg[(u + W - 1) * F2];  // row entering the window
        const uint64_t nvp = f2pk(nv.x, nv.y);

        const uint64_t ssp  = f2add(sp, nvp);
        const uint64_t ss2p = f2fma(nvp, nvp, s2p);

        const uint64_t meanp   = f2mul(ssp, invWp);
        const uint64_t nmeanp  = f2mul(ssp, ninvWp);
        const uint64_t meansqp = f2mul(ss2p, invWp);
        const uint64_t varp    = f2fma(nmeanp, meanp, meansqp);

        const float2 mean = f2up(meanp);
        float2 var = f2up(varp);
        var.x = fmaxf(var.x, 1e-12f);
        var.y = fmaxf(var.y, 1e-12f);

        // 1/(std+eps) ~= rs*(1-eps*rs), rs = rsqrt(var); rel err ~ eps^2/var.
        float rsx, rsy;
        asm("rsqrt.approx.f32 %0, %1;" : "=f"(rsx) : "f"(var.x));
        asm("rsqrt.approx.f32 %0, %1;" : "=f"(rsy) : "f"(var.y));

        float2 r;
        r.x = (nv.x - mean.x) * rsx * fmaf(-EPSF, rsx, 1.0f);
        r.y = (nv.y - mean.y) * rsy * fmaf(-EPSF, rsy, 1.0f);
        __stcs(op + (size_t)u * F2, r);          // STG.64 streaming store

        const float2 ov = sg[u * F2];            // row leaving the window
        const uint64_t ovp  = f2pk(ov.x, ov.y);
        const uint64_t novp = f2mul(ovp, neg1p);
        sp  = f2add(ssp, novp);                  // s  = ss  - ov
        s2p = f2fma(ovp, novp, ss2p);            // s2 = ss2 - ov*ov
    }
}

extern "C" void kernel_launch(void* const* d_in, const int* in_sizes, int n_in,
                              void* d_out, int out_size)
{
    (void)n_in; (void)out_size;
    const float* x = (const float*)d_in[0];
    float* out = (float*)d_out;

    cudaFuncSetAttribute(ts_zscore_kernel,
                         cudaFuncAttributeMaxDynamicSharedMemorySize, SMEM_BYTES);

    const int B = in_sizes[0] / (TT * FF);   // 64 for this problem
    dim3 block(F2, 2);                        // 128 threads
    dim3 grid(B, (NS + SEG - 1) / SEG);       // (64, 68)
    ts_zscore_kernel<<<grid, block, SMEM_BYTES>>>(x, out);
}